// round 7
// baseline (speedup 1.0000x reference)
#include <cuda_runtime.h>
#include <math.h>

// Problem constants: N=100000, L=48, E=1600000, ED=17, H=48
#define NN 100000
#define LL 48
#define EDD 17
#define EEMAX 1600000
#define CAP (1<<18)
#define NCAP (1<<16)
#define NBW 3136            // ceil(100000/32)=3125 padded to x4
#define GRID 148
#define TPB 1024
#define EPT 16              // edges per thread (148*1024*16 = 2.42M >= E)
#define FULL 0xffffffffu
#define SMEM_BYTES ((NBW + TPB * EPT) * 4)

__device__ float g_x[NN*LL];
__device__ float g_v[NN*LL];
__device__ float g_agg[NN*LL];          // invariant: all-zero between runs
__device__ float g_wbase[EEMAX];
__device__ __align__(16) unsigned int g_flag1b[NBW];
__device__ __align__(16) unsigned int g_flag2b[NBW];
__device__ int g_list2[CAP];
__device__ int g_list3[CAP];
__device__ int g_nlist1[NCAP];
__device__ int g_nlist2[NCAP];
__device__ int g_cnt[4];                // edge counts (2,3)
__device__ int g_ncnt[4];               // node counts (1,2)
__device__ volatile int g_bar[4];

__device__ __forceinline__ float geluf(float x) {
    return 0.5f * x * (1.0f + erff(x * 0.70710678118654752f));
}
__device__ __forceinline__ float sigm(float x) {
    return 1.0f / (1.0f + expf(-x));
}
__device__ __forceinline__ bool mark_bit(unsigned int* fw, int s) {
    unsigned int b = 1u << (s & 31);
    return (atomicOr(&fw[s >> 5], b) & b) == 0u;
}

// barrier: arrival = 1 atomic; poll = volatile plain load (no RMW contention)
__device__ __forceinline__ void gbar_wait(int idx) {
    __syncthreads();
    if (threadIdx.x == 0) {
        __threadfence();
        atomicAdd((int*)&g_bar[idx], 1);
        while (g_bar[idx] < GRID) __nanosleep(32);
        __threadfence();
    }
    __syncthreads();
}
__device__ __forceinline__ void gbar_arrive(int idx) {
    __syncthreads();
    if (threadIdx.x == 0) {
        __threadfence();
        atomicAdd((int*)&g_bar[idx], 1);
    }
}

// full-warp edge MLP: returns w_base on ALL lanes
__device__ __forceinline__ float edge_mlp(int eid, int lane, bool lo,
        const float* __restrict__ ea_all,
        const float* __restrict__ W1, const float* __restrict__ b1,
        const float* __restrict__ W2, const float* __restrict__ b2,
        const float* __restrict__ Wg, const float* __restrict__ bg,
        const float* __restrict__ Ww, float bw0) {
    const float* ea = ea_all + (long long)eid * EDD;

    float a  = b1[lane];
    float a2 = lo ? b1[lane + 32] : 0.f;
    #pragma unroll
    for (int k = 0; k < EDD; k++) {
        float ev = __ldg(&ea[k]);
        a = fmaf(ev, W1[k * 48 + lane], a);
        if (lo) a2 = fmaf(ev, W1[k * 48 + lane + 32], a2);
    }
    a = geluf(a); a2 = geluf(a2);

    float c  = b2[lane];
    float c2 = lo ? b2[lane + 32] : 0.f;
    #pragma unroll
    for (int k = 0; k < 48; k++) {
        float hk = (k < 32) ? __shfl_sync(FULL, a, k)
                            : __shfl_sync(FULL, a2, k - 32);
        c = fmaf(hk, W2[k * 48 + lane], c);
        if (lo) c2 = fmaf(hk, W2[k * 48 + lane + 32], c2);
    }
    c = fmaxf(c, 0.f); c2 = fmaxf(c2, 0.f);

    float d1 = bg[lane];
    float d2 = lo ? bg[lane + 32] : 0.f;
    #pragma unroll
    for (int k = 0; k < 48; k++) {
        float hk = (k < 32) ? __shfl_sync(FULL, c, k)
                            : __shfl_sync(FULL, c2, k - 32);
        d1 = fmaf(hk, Wg[k * 48 + lane], d1);
        if (lo) d2 = fmaf(hk, Wg[k * 48 + lane + 32], d2);
    }
    d1 = geluf(d1); d2 = geluf(d2);

    float p = d1 * Ww[lane] + (lo ? d2 * Ww[lane + 32] : 0.f);
    #pragma unroll
    for (int off = 16; off; off >>= 1) p += __shfl_xor_sync(FULL, p, off);
    return p + bw0;
}

__global__ void __launch_bounds__(TPB)
k_main(const int* __restrict__ src, const int* __restrict__ dst, int e,
       const float* __restrict__ nodes, const float* __restrict__ valid,
       const float* __restrict__ ea_all,
       const float* __restrict__ W1, const float* __restrict__ b1,
       const float* __restrict__ W2, const float* __restrict__ b2,
       const float* __restrict__ Wg, const float* __restrict__ bg,
       const float* __restrict__ Ww, const float* __restrict__ bw,
       const float* __restrict__ Wf, const float* __restrict__ bf,
       float* __restrict__ out) {
    extern __shared__ unsigned int smem_[];
    unsigned int* sflag = smem_;                 // NBW words
    int* sdst = (int*)(smem_ + NBW);             // TPB*EPT words, layout [t*TPB+tid]

    const int tid  = threadIdx.x;
    const int lane = tid & 31;
    const bool lo  = (lane < 16);
    const int gtid = blockIdx.x * TPB + tid;
    const int base = gtid * EPT;

    // ======== Phase 1: load dst chunk -> smem cache; scan3 (dst==0) ========
    int d[EPT];
    #pragma unroll
    for (int t = 0; t < EPT; t++) d[t] = -1;
    if (base < e) {
        if (base + EPT <= e) {
            int4 a0 = __ldg((const int4*)(dst + base));
            int4 a1 = __ldg((const int4*)(dst + base + 4));
            int4 a2 = __ldg((const int4*)(dst + base + 8));
            int4 a3 = __ldg((const int4*)(dst + base + 12));
            d[0]=a0.x; d[1]=a0.y; d[2]=a0.z; d[3]=a0.w;
            d[4]=a1.x; d[5]=a1.y; d[6]=a1.z; d[7]=a1.w;
            d[8]=a2.x; d[9]=a2.y; d[10]=a2.z; d[11]=a2.w;
            d[12]=a3.x; d[13]=a3.y; d[14]=a3.z; d[15]=a3.w;
        } else {
            #pragma unroll
            for (int t = 0; t < EPT; t++) if (base + t < e) d[t] = dst[base + t];
        }
    }
    #pragma unroll
    for (int t = 0; t < EPT; t++) sdst[t * TPB + tid] = d[t];

    // seed node 0 into both frontiers via the normal mark path
    if (gtid == 0) {
        if (mark_bit(g_flag2b, 0)) {
            int q = atomicAdd(&g_ncnt[2], 1);
            if (q < NCAP) g_nlist2[q] = 0;
        }
        if (mark_bit(g_flag1b, 0)) {
            int q = atomicAdd(&g_ncnt[1], 1);
            if (q < NCAP) g_nlist1[q] = 0;
        }
    }

    {
        int mymask = 0;
        #pragma unroll
        for (int t = 0; t < EPT; t++) if (d[t] == 0) mymask |= 1 << t;
        if (__ballot_sync(FULL, mymask != 0)) {
            #pragma unroll 1
            for (int t = 0; t < EPT; t++) {
                bool pred = (mymask >> t) & 1;
                unsigned int m = __ballot_sync(FULL, pred);
                if (!m) continue;
                int leader = __ffs(m) - 1;
                int pos0 = 0;
                if (lane == leader) pos0 = atomicAdd(&g_cnt[3], __popc(m));
                pos0 = __shfl_sync(FULL, pos0, leader);
                if (pred) {
                    int p = pos0 + __popc(m & ((1u << lane) - 1));
                    int eid = base + t;
                    if (p < CAP) g_list3[p] = eid;
                    int s = __ldg(&src[eid]);
                    if (mark_bit(g_flag2b, s)) {
                        int q = atomicAdd(&g_ncnt[2], 1);
                        if (q < NCAP) g_nlist2[q] = s;
                    }
                    if (mark_bit(g_flag1b, s)) {
                        int q = atomicAdd(&g_ncnt[1], 1);
                        if (q < NCAP) g_nlist1[q] = s;
                    }
                }
            }
        }
    }
    gbar_wait(0);

    // ======== Phase 2: stage flag2, scan2 from smem dst cache ========
    {
        const uint4* gs = (const uint4*)g_flag2b;
        uint4* sd = (uint4*)sflag;
        for (int i = tid; i < NBW / 4; i += TPB) sd[i] = __ldcg((const uint4*)&gs[i]);
    }
    __syncthreads();
    {
        int mymask = 0;
        #pragma unroll
        for (int t = 0; t < EPT; t++) {
            int dd = sdst[t * TPB + tid];
            d[t] = dd;
            if (dd >= 0 && ((sflag[dd >> 5] >> (dd & 31)) & 1u)) mymask |= 1 << t;
        }
        if (__ballot_sync(FULL, mymask != 0)) {
            #pragma unroll 1
            for (int t = 0; t < EPT; t++) {
                bool pred = (mymask >> t) & 1;
                unsigned int m = __ballot_sync(FULL, pred);
                if (!m) continue;
                int leader = __ffs(m) - 1;
                int pos0 = 0;
                if (lane == leader) pos0 = atomicAdd(&g_cnt[2], __popc(m));
                pos0 = __shfl_sync(FULL, pos0, leader);
                if (pred) {
                    int p = pos0 + __popc(m & ((1u << lane) - 1));
                    int eid = base + t;
                    if (p < CAP) g_list2[p] = eid;
                    int s = __ldg(&src[eid]);
                    if (mark_bit(g_flag1b, s)) {
                        int q = atomicAdd(&g_ncnt[1], 1);
                        if (q < NCAP) g_nlist1[q] = s;
                    }
                }
            }
        }
    }
    gbar_wait(1);

    // ======== Phase 3: stage flag1; scan1 + inline wbase + agg1 ========
    {
        const uint4* gs = (const uint4*)g_flag1b;
        uint4* sd = (uint4*)sflag;
        for (int i = tid; i < NBW / 4; i += TPB) sd[i] = __ldcg((const uint4*)&gs[i]);
    }
    __syncthreads();
    {
        float bw0 = __ldg(bw);
        int mymask = 0;
        #pragma unroll
        for (int t = 0; t < EPT; t++) {
            int dd = sdst[t * TPB + tid];
            if (dd >= 0 && ((sflag[dd >> 5] >> (dd & 31)) & 1u)) mymask |= 1 << t;
        }
        if (__ballot_sync(FULL, mymask != 0)) {
            #pragma unroll 1
            for (int t = 0; t < EPT; t++) {
                unsigned int m = __ballot_sync(FULL, (mymask >> t) & 1);
                while (m) {
                    int leader = __ffs(m) - 1;
                    m &= m - 1;
                    int eid = __shfl_sync(FULL, base, leader) + t;
                    // full-warp MLP for this edge
                    float wb = edge_mlp(eid, lane, lo, ea_all, W1, b1, W2, b2,
                                        Wg, bg, Ww, bw0);
                    if (lane == 0) g_wbase[eid] = wb;
                    // aggregate: x0/v0 computed on the fly
                    int s = __ldg(&src[eid]);
                    int dn = __ldg(&dst[eid]);
                    long long sb = (long long)s * LL;
                    float v0 = __ldg(&valid[sb + lane]);
                    float v1 = lo ? __ldg(&valid[sb + lane + 32]) : 0.f;
                    float x0 = __ldg(&nodes[sb + lane]) * v0;
                    float x1 = lo ? __ldg(&nodes[sb + lane + 32]) * v1 : 0.f;
                    float sv = v0 + v1;
                    #pragma unroll
                    for (int off = 16; off; off >>= 1)
                        sv += __shfl_xor_sync(FULL, sv, off);
                    float sg = sigm((sv * (1.0f / 48.0f)) * wb);
                    float* ad = g_agg + (long long)dn * LL;
                    atomicAdd(&ad[lane], x0 * sg);
                    if (lo) atomicAdd(&ad[lane + 32], x1 * sg);
                }
            }
        }
    }
    gbar_arrive(2);
    if (blockIdx.x != 0) return;        // 147 blocks done
    if (tid == 0) {
        while (g_bar[2] < GRID) __nanosleep(32);
        __threadfence();
    }
    __syncthreads();

    // ======== Block 0: upd1 -> (agg2,upd2) -> (agg3,upd3+out) -> reset ========
    float wf0 = __ldg(&Wf[0]), wf1 = __ldg(&Wf[1]), wf2 = __ldg(&Wf[2]);
    float b0 = __ldg(bf);

    // upd1 over nlist1 (also restores g_agg to zero)
    {
        int total = min(__ldcg(&g_ncnt[1]), NCAP) * LL;
        for (int q = tid; q < total; q += TPB) {
            int u = __ldcg(&g_nlist1[q / LL]);
            int l = q % LL;
            long long i = (long long)u * LL + l;
            float vo = __ldg(&valid[i]);
            float orig = __ldg(&nodes[i]) * vo;
            float xo = orig;
            float nh = __ldcg(&g_agg[i]);
            float nv = 1.0f - vo;
            float mm = sigm(nh * wf0 + xo * wf1 + nv * wf2 + b0);
            float xn = (1.0f - mm) * xo + nv * mm * nh;
            float vn = (l != 0 && (orig != xn || vo > 0.0f)) ? 1.0f : 0.0f;
            g_x[i] = xn;
            g_v[i] = vn;
            g_agg[i] = 0.f;
        }
    }
    __syncthreads();

    #pragma unroll 1
    for (int level = 2; level <= 3; level++) {
        const int* list = (level == 2) ? g_list2 : g_list3;
        int cnt = min(__ldcg(&g_cnt[level]), CAP);
        int warp = tid >> 5;
        for (int it = warp; it < cnt; it += (TPB >> 5)) {
            int eid = __ldcg(&list[it]);
            int s = __ldg(&src[eid]);
            int dn = __ldg(&dst[eid]);
            long long sb = (long long)s * LL;
            float v0 = g_v[sb + lane];
            float v1 = lo ? g_v[sb + lane + 32] : 0.f;
            float x0 = g_x[sb + lane];
            float x1 = lo ? g_x[sb + lane + 32] : 0.f;
            float sv = v0 + v1;
            #pragma unroll
            for (int off = 16; off; off >>= 1) sv += __shfl_xor_sync(FULL, sv, off);
            float sg = sigm((sv * (1.0f / 48.0f)) * __ldcg(&g_wbase[eid]));
            float* ad = g_agg + (long long)dn * LL;
            atomicAdd(&ad[lane], x0 * sg);
            if (lo) atomicAdd(&ad[lane + 32], x1 * sg);
        }
        __syncthreads();

        int ncnt = (level == 2) ? min(__ldcg(&g_ncnt[2]), NCAP) : 1;
        int total = ncnt * LL;
        for (int q = tid; q < total; q += TPB) {
            int u = (level == 2) ? __ldcg(&g_nlist2[q / LL]) : 0;
            int l = q % LL;
            long long i = (long long)u * LL + l;
            float vv = __ldg(&valid[i]);
            float orig = __ldg(&nodes[i]) * vv;
            float xo = g_x[i];
            float vo = g_v[i];
            float nh = __ldcg(&g_agg[i]);
            float nv = 1.0f - vo;
            float mm = sigm(nh * wf0 + xo * wf1 + nv * wf2 + b0);
            float xn = (1.0f - mm) * xo + nv * mm * nh;
            float vn = (l != 0 && (orig != xn || vo > 0.0f)) ? 1.0f : 0.0f;
            g_x[i] = xn;
            g_v[i] = vn;
            g_agg[i] = 0.f;
            if (level == 3) out[l] = xn;
        }
        __syncthreads();
    }

    // reset persistent state for the next (identical) replay
    for (int i = tid; i < NBW; i += TPB) {
        g_flag1b[i] = 0u;
        g_flag2b[i] = 0u;
    }
    if (tid < 4) {
        g_cnt[tid] = 0;
        g_ncnt[tid] = 0;
        ((int*)g_bar)[tid] = 0;
    }
}

extern "C" void kernel_launch(void* const* d_in, const int* in_sizes, int n_in,
                              void* d_out, int out_size) {
    const float* nodes     = (const float*)d_in[0];
    const int*   ei        = (const int*)d_in[1];
    const float* edge_attr = (const float*)d_in[2];
    const float* valid     = (const float*)d_in[3];
    const float* W1 = (const float*)d_in[6];
    const float* b1 = (const float*)d_in[7];
    const float* W2 = (const float*)d_in[8];
    const float* b2 = (const float*)d_in[9];
    const float* Wg = (const float*)d_in[10];
    const float* bg = (const float*)d_in[11];
    const float* Ww = (const float*)d_in[12];
    const float* bw = (const float*)d_in[13];
    const float* Wf = (const float*)d_in[14];
    const float* bf = (const float*)d_in[15];

    int e = in_sizes[1] / 2;
    const int* src = ei;
    const int* dst = ei + e;

    static int attr_done = 0;
    if (!attr_done) {
        cudaFuncSetAttribute(k_main, cudaFuncAttributeMaxDynamicSharedMemorySize,
                             SMEM_BYTES);
        attr_done = 1;
    }

    k_main<<<GRID, TPB, SMEM_BYTES>>>(src, dst, e, nodes, valid, edge_attr,
                                      W1, b1, W2, b2, Wg, bg, Ww, bw, Wf, bf,
                                      (float*)d_out);
}

// round 10
// speedup vs baseline: 1.1571x; 1.1571x over previous
#include <cuda_runtime.h>
#include <math.h>

// Problem constants: N=100000, L=48, E=1600000, ED=17, H=48
#define NN 100000
#define LL 48
#define EDD 17
#define EEMAX 1600000
#define CAP (1<<18)
#define NCAP (1<<16)
#define NBW 3136            // ceil(100000/32)=3125 padded to x4
#define GRID 148
#define TPB 1024
#define EPT 16              // 148*1024*16 = 2.42M >= E
#define FULL 0xffffffffu
#define SMEM_BYTES ((NBW + TPB * EPT) * 4)

__device__ float g_x[NN*LL];
__device__ float g_v[NN*LL];
__device__ float g_agg[NN*LL];          // invariant: all-zero between runs
__device__ float g_wbase[EEMAX];
__device__ __align__(16) unsigned int g_flag1b[NBW];
__device__ __align__(16) unsigned int g_flag2b[NBW];
__device__ int g_list1[CAP];
__device__ int g_list2[CAP];
__device__ int g_list3[CAP];
__device__ int g_nlist1[NCAP];
__device__ int g_nlist2[NCAP];
__device__ int g_cnt[4];
__device__ int g_ncnt[4];
__device__ volatile int g_bar[8];

__device__ __forceinline__ float geluf(float x) {
    return 0.5f * x * (1.0f + erff(x * 0.70710678118654752f));
}
__device__ __forceinline__ float sigm(float x) {
    return 1.0f / (1.0f + expf(-x));
}
__device__ __forceinline__ bool mark_bit(unsigned int* fw, int s) {
    unsigned int b = 1u << (s & 31);
    return (atomicOr(&fw[s >> 5], b) & b) == 0u;
}

// barrier: arrival = 1 atomic RMW; poll = volatile plain load
__device__ __forceinline__ void gbar_wait(int idx) {
    __syncthreads();
    if (threadIdx.x == 0) {
        __threadfence();
        atomicAdd((int*)&g_bar[idx], 1);
        while (g_bar[idx] < GRID) __nanosleep(32);
        __threadfence();
    }
    __syncthreads();
}
__device__ __forceinline__ void gbar_arrive(int idx) {
    __syncthreads();
    if (threadIdx.x == 0) {
        __threadfence();
        atomicAdd((int*)&g_bar[idx], 1);
    }
}

// full-warp edge MLP: returns w_base on ALL lanes
__device__ __forceinline__ float edge_mlp(int eid, int lane, bool lo,
        const float* __restrict__ ea_all,
        const float* __restrict__ W1, const float* __restrict__ b1,
        const float* __restrict__ W2, const float* __restrict__ b2,
        const float* __restrict__ Wg, const float* __restrict__ bg,
        const float* __restrict__ Ww, float bw0) {
    const float* ea = ea_all + (long long)eid * EDD;

    float a  = b1[lane];
    float a2 = lo ? b1[lane + 32] : 0.f;
    #pragma unroll
    for (int k = 0; k < EDD; k++) {
        float ev = __ldg(&ea[k]);
        a = fmaf(ev, W1[k * 48 + lane], a);
        if (lo) a2 = fmaf(ev, W1[k * 48 + lane + 32], a2);
    }
    a = geluf(a); a2 = geluf(a2);

    float c  = b2[lane];
    float c2 = lo ? b2[lane + 32] : 0.f;
    #pragma unroll
    for (int k = 0; k < 48; k++) {
        float hk = (k < 32) ? __shfl_sync(FULL, a, k)
                            : __shfl_sync(FULL, a2, k - 32);
        c = fmaf(hk, W2[k * 48 + lane], c);
        if (lo) c2 = fmaf(hk, W2[k * 48 + lane + 32], c2);
    }
    c = fmaxf(c, 0.f); c2 = fmaxf(c2, 0.f);

    float d1 = bg[lane];
    float d2 = lo ? bg[lane + 32] : 0.f;
    #pragma unroll
    for (int k = 0; k < 48; k++) {
        float hk = (k < 32) ? __shfl_sync(FULL, c, k)
                            : __shfl_sync(FULL, c2, k - 32);
        d1 = fmaf(hk, Wg[k * 48 + lane], d1);
        if (lo) d2 = fmaf(hk, Wg[k * 48 + lane + 32], d2);
    }
    d1 = geluf(d1); d2 = geluf(d2);

    float p = d1 * Ww[lane] + (lo ? d2 * Ww[lane + 32] : 0.f);
    #pragma unroll
    for (int off = 16; off; off >>= 1) p += __shfl_xor_sync(FULL, p, off);
    return p + bw0;
}

__global__ void __launch_bounds__(TPB)
k_main(const int* __restrict__ src, const int* __restrict__ dst, int e,
       const float* __restrict__ nodes, const float* __restrict__ valid,
       const float* __restrict__ ea_all,
       const float* __restrict__ W1, const float* __restrict__ b1,
       const float* __restrict__ W2, const float* __restrict__ b2,
       const float* __restrict__ Wg, const float* __restrict__ bg,
       const float* __restrict__ Ww, const float* __restrict__ bw,
       const float* __restrict__ Wf, const float* __restrict__ bf,
       float* __restrict__ out) {
    extern __shared__ unsigned int smem_[];
    unsigned int* sflag = smem_;                 // NBW words
    int* sdst = (int*)(smem_ + NBW);             // TPB*EPT words, layout [t*TPB+tid]

    const int tid  = threadIdx.x;
    const int lane = tid & 31;
    const bool lo  = (lane < 16);
    const int gtid = blockIdx.x * TPB + tid;
    const int base = gtid * EPT;
    const int gthreads = GRID * TPB;

    // ======== Phase 1: load dst -> regs + smem cache; scan3 (dst==0) ========
    int d[EPT];
    #pragma unroll
    for (int t = 0; t < EPT; t++) d[t] = -1;
    if (base < e) {
        if (base + EPT <= e) {
            int4 a0 = __ldg((const int4*)(dst + base));
            int4 a1 = __ldg((const int4*)(dst + base + 4));
            int4 a2 = __ldg((const int4*)(dst + base + 8));
            int4 a3 = __ldg((const int4*)(dst + base + 12));
            d[0]=a0.x; d[1]=a0.y; d[2]=a0.z; d[3]=a0.w;
            d[4]=a1.x; d[5]=a1.y; d[6]=a1.z; d[7]=a1.w;
            d[8]=a2.x; d[9]=a2.y; d[10]=a2.z; d[11]=a2.w;
            d[12]=a3.x; d[13]=a3.y; d[14]=a3.z; d[15]=a3.w;
        } else {
            #pragma unroll
            for (int t = 0; t < EPT; t++) if (base + t < e) d[t] = dst[base + t];
        }
    }
    #pragma unroll
    for (int t = 0; t < EPT; t++) sdst[t * TPB + tid] = d[t];

    // seed node 0 into both frontiers
    if (gtid == 0) {
        if (mark_bit(g_flag2b, 0)) {
            int q = atomicAdd(&g_ncnt[2], 1);
            if (q < NCAP) g_nlist2[q] = 0;
        }
        if (mark_bit(g_flag1b, 0)) {
            int q = atomicAdd(&g_ncnt[1], 1);
            if (q < NCAP) g_nlist1[q] = 0;
        }
    }

    {
        int mymask = 0;
        #pragma unroll
        for (int t = 0; t < EPT; t++) if (d[t] == 0) mymask |= 1 << t;
        if (__ballot_sync(FULL, mymask != 0)) {
            #pragma unroll 1
            for (int t = 0; t < EPT; t++) {
                bool pred = (mymask >> t) & 1;
                unsigned int m = __ballot_sync(FULL, pred);
                if (!m) continue;
                int leader = __ffs(m) - 1;
                int pos0 = 0;
                if (lane == leader) pos0 = atomicAdd(&g_cnt[3], __popc(m));
                pos0 = __shfl_sync(FULL, pos0, leader);
                if (pred) {
                    int p = pos0 + __popc(m & ((1u << lane) - 1));
                    int eid = base + t;
                    if (p < CAP) g_list3[p] = eid;
                    int s = __ldg(&src[eid]);
                    if (mark_bit(g_flag2b, s)) {
                        int q = atomicAdd(&g_ncnt[2], 1);
                        if (q < NCAP) g_nlist2[q] = s;
                    }
                    if (mark_bit(g_flag1b, s)) {
                        int q = atomicAdd(&g_ncnt[1], 1);
                        if (q < NCAP) g_nlist1[q] = s;
                    }
                }
            }
        }
    }
    gbar_wait(0);

    // ======== Phase 2: stage flag2, scan2 from smem dst cache ========
    {
        const uint4* gs = (const uint4*)g_flag2b;
        uint4* sd = (uint4*)sflag;
        for (int i = tid; i < NBW / 4; i += TPB) sd[i] = __ldcg(&gs[i]);
    }
    __syncthreads();
    {
        int mymask = 0;
        #pragma unroll
        for (int t = 0; t < EPT; t++) {
            int dd = sdst[t * TPB + tid];
            if (dd >= 0 && ((sflag[dd >> 5] >> (dd & 31)) & 1u)) mymask |= 1 << t;
        }
        if (__ballot_sync(FULL, mymask != 0)) {
            #pragma unroll 1
            for (int t = 0; t < EPT; t++) {
                bool pred = (mymask >> t) & 1;
                unsigned int m = __ballot_sync(FULL, pred);
                if (!m) continue;
                int leader = __ffs(m) - 1;
                int pos0 = 0;
                if (lane == leader) pos0 = atomicAdd(&g_cnt[2], __popc(m));
                pos0 = __shfl_sync(FULL, pos0, leader);
                if (pred) {
                    int p = pos0 + __popc(m & ((1u << lane) - 1));
                    int eid = base + t;
                    if (p < CAP) g_list2[p] = eid;
                    int s = __ldg(&src[eid]);
                    if (mark_bit(g_flag1b, s)) {
                        int q = atomicAdd(&g_ncnt[1], 1);
                        if (q < NCAP) g_nlist1[q] = s;
                    }
                }
            }
        }
    }
    gbar_wait(1);

    // ======== Phase 3: stage flag1, scan1 -> list1 ========
    {
        const uint4* gs = (const uint4*)g_flag1b;
        uint4* sd = (uint4*)sflag;
        for (int i = tid; i < NBW / 4; i += TPB) sd[i] = __ldcg(&gs[i]);
    }
    __syncthreads();
    {
        int mymask = 0;
        #pragma unroll
        for (int t = 0; t < EPT; t++) {
            int dd = sdst[t * TPB + tid];
            if (dd >= 0 && ((sflag[dd >> 5] >> (dd & 31)) & 1u)) mymask |= 1 << t;
        }
        if (__ballot_sync(FULL, mymask != 0)) {
            #pragma unroll 1
            for (int t = 0; t < EPT; t++) {
                bool pred = (mymask >> t) & 1;
                unsigned int m = __ballot_sync(FULL, pred);
                if (!m) continue;
                int leader = __ffs(m) - 1;
                int pos0 = 0;
                if (lane == leader) pos0 = atomicAdd(&g_cnt[1], __popc(m));
                pos0 = __shfl_sync(FULL, pos0, leader);
                if (pred) {
                    int p = pos0 + __popc(m & ((1u << lane) - 1));
                    if (p < CAP) g_list1[p] = base + t;
                }
            }
        }
    }
    gbar_wait(2);

    // ======== Phase 4: balanced wbase + agg1 over list1 (warp/edge) ========
    {
        int gwarp = gtid >> 5;
        int nwarp = gthreads >> 5;
        int cnt = min(__ldcg(&g_cnt[1]), CAP);
        float bw0 = __ldg(bw);

        for (int it = gwarp; it < cnt; it += nwarp) {
            int eid = __ldcg(&g_list1[it]);
            float wb = edge_mlp(eid, lane, lo, ea_all, W1, b1, W2, b2,
                                Wg, bg, Ww, bw0);
            if (lane == 0) g_wbase[eid] = wb;

            int s = __ldg(&src[eid]);
            int dn = __ldg(&dst[eid]);
            long long sb = (long long)s * LL;
            float v0 = __ldg(&valid[sb + lane]);
            float v1 = lo ? __ldg(&valid[sb + lane + 32]) : 0.f;
            float x0 = __ldg(&nodes[sb + lane]) * v0;
            float x1 = lo ? __ldg(&nodes[sb + lane + 32]) * v1 : 0.f;
            float sv = v0 + v1;
            #pragma unroll
            for (int off = 16; off; off >>= 1) sv += __shfl_xor_sync(FULL, sv, off);
            float sg = sigm((sv * (1.0f / 48.0f)) * wb);
            float* ad = g_agg + (long long)dn * LL;
            atomicAdd(&ad[lane], x0 * sg);
            if (lo) atomicAdd(&ad[lane + 32], x1 * sg);
        }
    }
    gbar_wait(3);

    // ======== Phase 5: grid-wide upd1 over nlist1 (restores agg=0) ========
    {
        float wf0 = __ldg(&Wf[0]), wf1 = __ldg(&Wf[1]), wf2 = __ldg(&Wf[2]);
        float b0 = __ldg(bf);
        int total = min(__ldcg(&g_ncnt[1]), NCAP) * LL;
        for (int q = gtid; q < total; q += gthreads) {
            int u = __ldcg(&g_nlist1[q / LL]);
            int l = q % LL;
            long long i = (long long)u * LL + l;
            float vo = __ldg(&valid[i]);
            float orig = __ldg(&nodes[i]) * vo;
            float xo = orig;
            float nh = __ldcg(&g_agg[i]);
            float nv = 1.0f - vo;
            float mm = sigm(nh * wf0 + xo * wf1 + nv * wf2 + b0);
            float xn = (1.0f - mm) * xo + nv * mm * nh;
            float vn = (l != 0 && (orig != xn || vo > 0.0f)) ? 1.0f : 0.0f;
            g_x[i] = xn;
            g_v[i] = vn;
            g_agg[i] = 0.f;
        }
    }
    gbar_arrive(4);

    // ======== Epilogue ========
    if (blockIdx.x != 0) {
        // parallel flag reset by the 147 exiting blocks (flags unused after P3)
        int per = (NBW + GRID - 2) / (GRID - 1);     // slice among blocks 1..147
        int s0 = (blockIdx.x - 1) * per;
        int s1 = min(s0 + per, NBW);
        for (int i = s0 + tid; i < s1; i += TPB) {
            g_flag1b[i] = 0u;
            g_flag2b[i] = 0u;
        }
        return;
    }
    if (tid == 0) {
        while (g_bar[4] < GRID) __nanosleep(32);
        __threadfence();
    }
    __syncthreads();

    // Block 0: tail levels 2 and 3 (tiny), then reset counters/barriers
    float wf0 = __ldg(&Wf[0]), wf1 = __ldg(&Wf[1]), wf2 = __ldg(&Wf[2]);
    float b0 = __ldg(bf);

    #pragma unroll 1
    for (int level = 2; level <= 3; level++) {
        const int* list = (level == 2) ? g_list2 : g_list3;
        int cnt = min(__ldcg(&g_cnt[level]), CAP);
        int warp = tid >> 5;
        for (int it = warp; it < cnt; it += (TPB >> 5)) {
            int eid = __ldcg(&list[it]);
            int s = __ldg(&src[eid]);
            int dn = __ldg(&dst[eid]);
            long long sb = (long long)s * LL;
            float v0 = g_v[sb + lane];
            float v1 = lo ? g_v[sb + lane + 32] : 0.f;
            float x0 = g_x[sb + lane];
            float x1 = lo ? g_x[sb + lane + 32] : 0.f;
            float sv = v0 + v1;
            #pragma unroll
            for (int off = 16; off; off >>= 1) sv += __shfl_xor_sync(FULL, sv, off);
            float sg = sigm((sv * (1.0f / 48.0f)) * __ldcg(&g_wbase[eid]));
            float* ad = g_agg + (long long)dn * LL;
            atomicAdd(&ad[lane], x0 * sg);
            if (lo) atomicAdd(&ad[lane + 32], x1 * sg);
        }
        __syncthreads();

        int ncnt = (level == 2) ? min(__ldcg(&g_ncnt[2]), NCAP) : 1;
        int total = ncnt * LL;
        for (int q = tid; q < total; q += TPB) {
            int u = (level == 2) ? __ldcg(&g_nlist2[q / LL]) : 0;
            int l = q % LL;
            long long i = (long long)u * LL + l;
            float vv = __ldg(&valid[i]);
            float orig = __ldg(&nodes[i]) * vv;
            float xo = g_x[i];
            float vo = g_v[i];
            float nh = __ldcg(&g_agg[i]);
            float nv = 1.0f - vo;
            float mm = sigm(nh * wf0 + xo * wf1 + nv * wf2 + b0);
            float xn = (1.0f - mm) * xo + nv * mm * nh;
            float vn = (l != 0 && (orig != xn || vo > 0.0f)) ? 1.0f : 0.0f;
            g_x[i] = xn;
            g_v[i] = vn;
            g_agg[i] = 0.f;
            if (level == 3) out[l] = xn;
        }
        __syncthreads();
    }

    // reset state for next replay (block 1..147 handled flags; block 0 has no slice)
    if (tid < 4) {
        g_cnt[tid] = 0;
        g_ncnt[tid] = 0;
    }
    if (tid >= 4 && tid < 12) ((int*)g_bar)[tid - 4] = 0;
}

extern "C" void kernel_launch(void* const* d_in, const int* in_sizes, int n_in,
                              void* d_out, int out_size) {
    const float* nodes     = (const float*)d_in[0];
    const int*   ei        = (const int*)d_in[1];
    const float* edge_attr = (const float*)d_in[2];
    const float* valid     = (const float*)d_in[3];
    const float* W1 = (const float*)d_in[6];
    const float* b1 = (const float*)d_in[7];
    const float* W2 = (const float*)d_in[8];
    const float* b2 = (const float*)d_in[9];
    const float* Wg = (const float*)d_in[10];
    const float* bg = (const float*)d_in[11];
    const float* Ww = (const float*)d_in[12];
    const float* bw = (const float*)d_in[13];
    const float* Wf = (const float*)d_in[14];
    const float* bf = (const float*)d_in[15];

    int e = in_sizes[1] / 2;
    const int* src = ei;
    const int* dst = ei + e;

    static int attr_done = 0;
    if (!attr_done) {
        cudaFuncSetAttribute(k_main, cudaFuncAttributeMaxDynamicSharedMemorySize,
                             SMEM_BYTES);
        attr_done = 1;
    }

    k_main<<<GRID, TPB, SMEM_BYTES>>>(src, dst, e, nodes, valid, edge_attr,
                                      W1, b1, W2, b2, Wg, bg, Ww, bw, Wf, bf,
                                      (float*)d_out);
}